// round 16
// baseline (speedup 1.0000x reference)
#include <cuda_runtime.h>
#include <math.h>

#define N_NODES 50000
#define N_EDGES 800000
#define FILL_BLOCKS 3125          // ceil(800000/256)
#define LIN1_BLOCKS 6250          // 50000 nodes / 8 warps per block

#define INV_SQRT8  0.35355339059327373f
#define INV_SQRT32 0.17677669529663687f
#define CG_INV3    0.5773502691896258f   // 1/sqrt(3)
#define CG_INV2    0.7071067811865476f   // 1/sqrt(2)
#define MS_SCALE   0.125f                // 1/sqrt(64)
#define MV_SCALE   0.10206207261596575f  // 1/sqrt(96)
#define NSC_SCALE  0.0625f               // 1/sqrt(256)
#define NEIGH_INV  0.25f                 // 1/sqrt(16)

typedef unsigned long long u64;

// Scratch (static device memory — zero-initialized at module load)
__device__ __align__(16) float g_xs[N_NODES * 32];
__device__ __align__(16) float g_xv[N_NODES * 96];    // [N][3][32] comp-major
__device__ __align__(16) float g_aggs[N_NODES * 64];
__device__ __align__(16) float g_aggv[N_NODES * 288]; // [N][3][96] comp-major
__device__ int g_cnt[N_NODES];      // re-zeroed by scan_kernel each call
__device__ int g_off[N_NODES + 1];
__device__ int g_cur[N_NODES];
__device__ int g_psrc[N_EDGES];
__device__ __align__(16) float  g_ph[N_EDGES * 8];    // silu(emb@Wm1/sqrt8), CSR order
__device__ __align__(16) float4 g_psh[N_EDGES];

// ---- f32x2 packed helpers ----
__device__ __forceinline__ u64 pk2(float x) {
    u64 r;
    asm("mov.b64 %0, {%1, %1};" : "=l"(r) : "f"(x));
    return r;
}
__device__ __forceinline__ void fma2(u64& d, u64 a, u64 b) {
    asm("fma.rn.f32x2 %0, %1, %2, %0;" : "+l"(d) : "l"(a), "l"(b));
}
__device__ __forceinline__ u64 fma2r(u64 a, u64 b, u64 c) {
    u64 r;
    asm("fma.rn.f32x2 %0, %1, %2, %3;" : "=l"(r) : "l"(a), "l"(b), "l"(c));
    return r;
}
__device__ __forceinline__ u64 mul2(u64 a, u64 b) {
    u64 r;
    asm("mul.rn.f32x2 %0, %1, %2;" : "=l"(r) : "l"(a), "l"(b));
    return r;
}
__device__ __forceinline__ u64 add2(u64 a, u64 b) {
    u64 r;
    asm("add.rn.f32x2 %0, %1, %2;" : "=l"(r) : "l"(a), "l"(b));
    return r;
}

// ---------------------------------------------------------------------------
// Launch 1: count edges per destination
// ---------------------------------------------------------------------------
__global__ void count_kernel(const int* __restrict__ dst) {
    int e = blockIdx.x * blockDim.x + threadIdx.x;
    if (e < N_EDGES) atomicAdd(&g_cnt[dst[e]], 1);
}

// ---------------------------------------------------------------------------
// Launch 2: exclusive scan (hierarchical shuffle) + re-zero g_cnt
// ---------------------------------------------------------------------------
__global__ void scan_kernel() {
    __shared__ int wsum[32];
    const int CH = (N_NODES + 1023) / 1024;   // 49
    const int t = threadIdx.x;
    const int lo = t * CH;
    const int hi = min(lo + CH, N_NODES);
    int s = 0;
    for (int i = lo; i < hi; i++) s += g_cnt[i];

    const int lane = t & 31, wid = t >> 5;
    int v = s;
#pragma unroll
    for (int d = 1; d < 32; d <<= 1) {
        int o = __shfl_up_sync(0xffffffffu, v, d);
        if (lane >= d) v += o;
    }
    if (lane == 31) wsum[wid] = v;
    __syncthreads();
    if (wid == 0) {
        int w = wsum[lane];
#pragma unroll
        for (int d = 1; d < 32; d <<= 1) {
            int o = __shfl_up_sync(0xffffffffu, w, d);
            if (lane >= d) w += o;
        }
        wsum[lane] = w;
    }
    __syncthreads();
    int run = v - s + (wid ? wsum[wid - 1] : 0);
    for (int i = lo; i < hi; i++) {
        g_off[i] = run;
        g_cur[i] = run;
        run += g_cnt[i];
    }
    for (int i = lo; i < hi; i++) g_cnt[i] = 0;   // ready for next replay
    if (t == 0) g_off[N_NODES] = N_EDGES;
}

// ---------------------------------------------------------------------------
// Launch 3: MERGED fill (CSR permute + radial-MLP layer 1 + silu) + lin1.
// Blocks [0, FILL_BLOCKS) do fill; the rest do lin1 (one warp per node).
// ---------------------------------------------------------------------------
__global__ void fill_lin1_kernel(const int* __restrict__ dst,
                                 const int* __restrict__ src,
                                 const float* __restrict__ emb,
                                 const float* __restrict__ sh0,
                                 const float* __restrict__ sh1,
                                 const float* __restrict__ Wm1,
                                 const float* __restrict__ node_s,
                                 const float* __restrict__ node_v,
                                 const float* __restrict__ W1s,
                                 const float* __restrict__ W1v) {
    __shared__ float sW[2048];
    __shared__ float sWm1[64];

    if (blockIdx.x < FILL_BLOCKS) {
        if (threadIdx.x < 64) sWm1[threadIdx.x] = Wm1[threadIdx.x];
        __syncthreads();

        int e = blockIdx.x * blockDim.x + threadIdx.x;
        if (e >= N_EDGES) return;
        int p = atomicAdd(&g_cur[dst[e]], 1);
        g_psrc[p] = src[e];

        const float4 e0 = *reinterpret_cast<const float4*>(emb + e * 8);
        const float4 e1 = *reinterpret_cast<const float4*>(emb + e * 8 + 4);
        const float em[8] = {e0.x, e0.y, e0.z, e0.w, e1.x, e1.y, e1.z, e1.w};

        float hh[8];
#pragma unroll
        for (int j = 0; j < 8; j++) {
            float a = 0.f;
#pragma unroll
            for (int k = 0; k < 8; k++)
                a += em[k] * sWm1[k * 8 + j];
            a *= INV_SQRT8;
            hh[j] = a / (1.f + expf(-a));   // silu (accurate exp)
        }
        float4* pw = reinterpret_cast<float4*>(g_ph + p * 8);
        pw[0] = make_float4(hh[0], hh[1], hh[2], hh[3]);
        pw[1] = make_float4(hh[4], hh[5], hh[6], hh[7]);

        g_psh[p] = make_float4(sh0[e], sh1[e * 3 + 0], sh1[e * 3 + 1], sh1[e * 3 + 2]);
    } else {
        float* sW1s = sW;
        float* sW1v = sW + 1024;
        for (int i = threadIdx.x; i < 1024; i += blockDim.x) {
            sW1s[i] = W1s[i];
            sW1v[i] = W1v[i];
        }
        __syncthreads();

        const int warp = (blockIdx.x - FILL_BLOCKS) * (blockDim.x >> 5) + (threadIdx.x >> 5);
        const int lane = threadIdx.x & 31;
        if (warp >= N_NODES) return;
        const int n = warp;

        float sl = node_s[n * 32 + lane];
        float acc = 0.f;
#pragma unroll
        for (int u = 0; u < 32; u++)
            acc += __shfl_sync(0xffffffffu, sl, u) * sW1s[u * 32 + lane];
        g_xs[n * 32 + lane] = acc * INV_SQRT32;

#pragma unroll
        for (int c = 0; c < 3; c++) {
            float vl = node_v[n * 96 + lane * 3 + c];
            float a = 0.f;
#pragma unroll
            for (int u = 0; u < 32; u++)
                a += __shfl_sync(0xffffffffu, vl, u) * sW1v[u * 32 + lane];
            g_xv[n * 96 + c * 32 + lane] = a * INV_SQRT32;
        }
    }
}

// ---------------------------------------------------------------------------
// Launch 4 (PROFILED SLOT): gather_tp.
// WARP PER NODE: lane = es*16 + sub; 2 edge-slots x 16 channel-pair subs
// (u0 = sub*2, one f32x2 pair per thread -> 11 packed accumulators).
// __launch_bounds__(256, 3) caps regs at 85 -> 3 blocks/SM (24 warps, 37.5%).
// h precomputed in fill (no shuffles, straight-line loop body).
// Weight LDS: 16 distinct 8B = 128B/warp -> 1 wavefront each.
// CG_INV3 folded into Wm2 path 1, CG_INV2 into path 4 at staging time.
// ---------------------------------------------------------------------------
__global__ __launch_bounds__(256, 3) void gather_tp(const float* __restrict__ Wm2) {
    __shared__ __align__(16) float sWm2[1280];
    for (int i = threadIdx.x; i < 1280; i += blockDim.x) {
        const int p = (i % 160) >> 5;
        float sc = INV_SQRT8 * NEIGH_INV;
        if (p == 1) sc *= CG_INV3;
        if (p == 4) sc *= CG_INV2;
        sWm2[i] = Wm2[i] * sc;
    }
    __syncthreads();

    const int warp = (blockIdx.x * blockDim.x + threadIdx.x) >> 5;
    if (warp >= N_NODES) return;
    const int n = warp;
    const int lane = threadIdx.x & 31;
    const int es  = lane >> 4;       // edge slot 0..1
    const int sub = lane & 15;       // channel pair 0..15
    const int u0 = sub * 2;

    const int beg = g_off[n];
    const int end = g_off[n + 1];

    u64 A1 = 0, A2 = 0;
    u64 A3[3] = {0, 0, 0}, A4[3] = {0, 0, 0}, A5[3] = {0, 0, 0};

    for (int i = beg + es; i < end; i += 2) {
        const float4 h0 = *reinterpret_cast<const float4*>(g_ph + i * 8);
        const float4 h1 = *reinterpret_cast<const float4*>(g_ph + i * 8 + 4);
        const float4 sh = g_psh[i];
        const int ns = g_psrc[i];

        // feature loads issued early (independent of matvec)
        const u64 S  = *reinterpret_cast<const u64*>(g_xs + ns * 32 + u0);
        const u64 VX = *reinterpret_cast<const u64*>(g_xv + ns * 96 + u0);
        const u64 VY = *reinterpret_cast<const u64*>(g_xv + ns * 96 + 32 + u0);
        const u64 VZ = *reinterpret_cast<const u64*>(g_xv + ns * 96 + 64 + u0);

        // ---- layer-2 matvec (one channel pair) ----
        const float hv[8] = {h0.x, h0.y, h0.z, h0.w, h1.x, h1.y, h1.z, h1.w};
        u64 w[5] = {0, 0, 0, 0, 0};
#pragma unroll
        for (int k = 0; k < 8; k++) {
            const u64 hk2 = pk2(hv[k]);
            const float* base = sWm2 + k * 160 + u0;
#pragma unroll
            for (int p = 0; p < 5; p++)
                fma2(w[p], hk2, *reinterpret_cast<const u64*>(base + p * 32));
        }

        // ---- CG paths ----
        const u64 q02 = pk2(sh.x);
        const u64 x2  = pk2(sh.y), y2 = pk2(sh.z), z2 = pk2(sh.w);
        const u64 nx2 = pk2(-sh.y), ny2 = pk2(-sh.z), nz2 = pk2(-sh.w);

        const u64 dot = fma2r(VX, x2, fma2r(VY, y2, mul2(VZ, z2)));
        const u64 cx = fma2r(VZ, ny2, mul2(VY, z2));   // vy*s1z - vz*s1y
        const u64 cy = fma2r(VX, nz2, mul2(VZ, x2));   // vz*s1x - vx*s1z
        const u64 cz = fma2r(VY, nx2, mul2(VX, y2));   // vx*s1y - vy*s1x

        const u64 t1 = mul2(w[0], S);
        fma2(A1, t1, q02);
        fma2(A2, w[1], dot);
        const u64 t3 = mul2(w[2], S);
        fma2(A3[0], t3, x2); fma2(A3[1], t3, y2); fma2(A3[2], t3, z2);
        const u64 t4 = mul2(w[3], q02);
        fma2(A4[0], t4, VX); fma2(A4[1], t4, VY); fma2(A4[2], t4, VZ);
        fma2(A5[0], w[4], cx); fma2(A5[1], w[4], cy); fma2(A5[2], w[4], cz);
    }

    // ---- butterfly reduce across the 2 edge slots (xor 16) ----
#define RED2(v) v = add2(v, __shfl_xor_sync(0xffffffffu, v, 16));
    RED2(A1) RED2(A2)
#pragma unroll
    for (int c = 0; c < 3; c++) {
        RED2(A3[c]) RED2(A4[c]) RED2(A5[c])
    }
#undef RED2

    if (es == 0) {
        *reinterpret_cast<u64*>(g_aggs + n * 64 + u0)      = A1;
        *reinterpret_cast<u64*>(g_aggs + n * 64 + 32 + u0) = A2;
#pragma unroll
        for (int c = 0; c < 3; c++) {
            float* av_base = g_aggv + n * 288 + c * 96 + u0;
            *reinterpret_cast<u64*>(av_base)      = A3[c];
            *reinterpret_cast<u64*>(av_base + 32) = A4[c];
            *reinterpret_cast<u64*>(av_base + 64) = A5[c];
        }
    }
}

// ---------------------------------------------------------------------------
// Launch 5: scalar output (2 nodes x 8 channels per thread)
// ---------------------------------------------------------------------------
__global__ __launch_bounds__(256) void node_s_kernel(
        const float* __restrict__ node_s,
        const float* __restrict__ attrs,
        const float* __restrict__ W2s,
        const float* __restrict__ Wscs,
        float* __restrict__ out) {
    extern __shared__ float sw[];
    float* sW2s  = sw;          // 2048 floats
    float* sWscs = sw + 2048;   // 8192 floats
    for (int i = threadIdx.x; i < 2048; i += blockDim.x)
        sW2s[i] = W2s[i] * MS_SCALE;
    for (int i = threadIdx.x; i < 8192; i += blockDim.x)
        sWscs[i] = Wscs[i] * NSC_SCALE;
    __syncthreads();

    const int gt = blockIdx.x * blockDim.x + threadIdx.x;
    const int pair = gt >> 2;
    if (pair >= N_NODES / 2) return;
    const int ch0 = (gt & 3) * 8;
    const int n0 = pair * 2;
    const int n1 = n0 + 1;

    float acc0[8], acc1[8];
#pragma unroll
    for (int j = 0; j < 8; j++) { acc0[j] = 0.f; acc1[j] = 0.f; }

    const float4* inA = reinterpret_cast<const float4*>(g_aggs + n0 * 64);
    const float4* inB = reinterpret_cast<const float4*>(g_aggs + n1 * 64);
#pragma unroll 4
    for (int k4 = 0; k4 < 16; k4++) {
        const float4 av = inA[k4];
        const float4 bv = inB[k4];
        const float a[4] = {av.x, av.y, av.z, av.w};
        const float b[4] = {bv.x, bv.y, bv.z, bv.w};
#pragma unroll
        for (int j = 0; j < 4; j++) {
            const float4* wr = reinterpret_cast<const float4*>(sW2s + (k4 * 4 + j) * 32 + ch0);
            const float4 w0 = wr[0];
            const float4 w1 = wr[1];
            acc0[0] += a[j] * w0.x; acc0[1] += a[j] * w0.y;
            acc0[2] += a[j] * w0.z; acc0[3] += a[j] * w0.w;
            acc0[4] += a[j] * w1.x; acc0[5] += a[j] * w1.y;
            acc0[6] += a[j] * w1.z; acc0[7] += a[j] * w1.w;
            acc1[0] += b[j] * w0.x; acc1[1] += b[j] * w0.y;
            acc1[2] += b[j] * w0.z; acc1[3] += b[j] * w0.w;
            acc1[4] += b[j] * w1.x; acc1[5] += b[j] * w1.y;
            acc1[6] += b[j] * w1.z; acc1[7] += b[j] * w1.w;
        }
    }

    float at0[8], at1[8];
    {
        const float4 a0 = *reinterpret_cast<const float4*>(attrs + n0 * 8);
        const float4 a1 = *reinterpret_cast<const float4*>(attrs + n0 * 8 + 4);
        at0[0]=a0.x; at0[1]=a0.y; at0[2]=a0.z; at0[3]=a0.w;
        at0[4]=a1.x; at0[5]=a1.y; at0[6]=a1.z; at0[7]=a1.w;
        const float4 b0 = *reinterpret_cast<const float4*>(attrs + n1 * 8);
        const float4 b1 = *reinterpret_cast<const float4*>(attrs + n1 * 8 + 4);
        at1[0]=b0.x; at1[1]=b0.y; at1[2]=b0.z; at1[3]=b0.w;
        at1[4]=b1.x; at1[5]=b1.y; at1[6]=b1.z; at1[7]=b1.w;
    }
    const float4* nsA = reinterpret_cast<const float4*>(node_s + n0 * 32);
    const float4* nsB = reinterpret_cast<const float4*>(node_s + n1 * 32);
#pragma unroll 2
    for (int u4 = 0; u4 < 8; u4++) {
        const float4 sa = nsA[u4];
        const float4 sb = nsB[u4];
        const float sua[4] = {sa.x, sa.y, sa.z, sa.w};
        const float sub_[4] = {sb.x, sb.y, sb.z, sb.w};
#pragma unroll
        for (int j = 0; j < 4; j++) {
            const int u = u4 * 4 + j;
#pragma unroll
            for (int a = 0; a < 8; a++) {
                const float za = sua[j] * at0[a];
                const float zb = sub_[j] * at1[a];
                const float4* wr = reinterpret_cast<const float4*>(sWscs + (u * 8 + a) * 32 + ch0);
                const float4 w0 = wr[0];
                const float4 w1 = wr[1];
                acc0[0] += za * w0.x; acc0[1] += za * w0.y;
                acc0[2] += za * w0.z; acc0[3] += za * w0.w;
                acc0[4] += za * w1.x; acc0[5] += za * w1.y;
                acc0[6] += za * w1.z; acc0[7] += za * w1.w;
                acc1[0] += zb * w0.x; acc1[1] += zb * w0.y;
                acc1[2] += zb * w0.z; acc1[3] += zb * w0.w;
                acc1[4] += zb * w1.x; acc1[5] += zb * w1.y;
                acc1[6] += zb * w1.z; acc1[7] += zb * w1.w;
            }
        }
    }

    float4* o0 = reinterpret_cast<float4*>(out + n0 * 128 + ch0);
    o0[0] = make_float4(acc0[0], acc0[1], acc0[2], acc0[3]);
    o0[1] = make_float4(acc0[4], acc0[5], acc0[6], acc0[7]);
    float4* o1 = reinterpret_cast<float4*>(out + n1 * 128 + ch0);
    o1[0] = make_float4(acc1[0], acc1[1], acc1[2], acc1[3]);
    o1[1] = make_float4(acc1[4], acc1[5], acc1[6], acc1[7]);
}

// ---------------------------------------------------------------------------
// Launch 6: vector output (2 nodes x 4 channels per thread)
// ---------------------------------------------------------------------------
__global__ __launch_bounds__(256) void node_v_kernel(
        const float* __restrict__ node_v,
        const float* __restrict__ attrs,
        const float* __restrict__ W2v,
        const float* __restrict__ Wscv,
        float* __restrict__ out) {
    extern __shared__ float sw[];
    float* sW2v  = sw;          // 3072 floats
    float* sWscv = sw + 3072;   // 8192 floats
    for (int i = threadIdx.x; i < 3072; i += blockDim.x)
        sW2v[i] = W2v[i] * MV_SCALE;
    for (int i = threadIdx.x; i < 8192; i += blockDim.x)
        sWscv[i] = Wscv[i] * NSC_SCALE;
    __syncthreads();

    const int gt = blockIdx.x * blockDim.x + threadIdx.x;
    const int pair = gt >> 3;
    if (pair >= N_NODES / 2) return;
    const int ch0 = (gt & 7) * 4;
    const int n0 = pair * 2;
    const int n1 = n0 + 1;

    float accv0[3][4], accv1[3][4];
#pragma unroll
    for (int c = 0; c < 3; c++)
#pragma unroll
        for (int j = 0; j < 4; j++) { accv0[c][j] = 0.f; accv1[c][j] = 0.f; }

    const float4* iA0 = reinterpret_cast<const float4*>(g_aggv + n0 * 288);
    const float4* iA1 = reinterpret_cast<const float4*>(g_aggv + n0 * 288 + 96);
    const float4* iA2 = reinterpret_cast<const float4*>(g_aggv + n0 * 288 + 192);
    const float4* iB0 = reinterpret_cast<const float4*>(g_aggv + n1 * 288);
    const float4* iB1 = reinterpret_cast<const float4*>(g_aggv + n1 * 288 + 96);
    const float4* iB2 = reinterpret_cast<const float4*>(g_aggv + n1 * 288 + 192);
#pragma unroll 2
    for (int k4 = 0; k4 < 24; k4++) {
        const float4 a0 = iA0[k4], a1 = iA1[k4], a2 = iA2[k4];
        const float4 b0 = iB0[k4], b1 = iB1[k4], b2 = iB2[k4];
        const float fa0[4] = {a0.x, a0.y, a0.z, a0.w};
        const float fa1[4] = {a1.x, a1.y, a1.z, a1.w};
        const float fa2[4] = {a2.x, a2.y, a2.z, a2.w};
        const float fb0[4] = {b0.x, b0.y, b0.z, b0.w};
        const float fb1[4] = {b1.x, b1.y, b1.z, b1.w};
        const float fb2[4] = {b2.x, b2.y, b2.z, b2.w};
#pragma unroll
        for (int j = 0; j < 4; j++) {
            const float4 w = *reinterpret_cast<const float4*>(sW2v + (k4 * 4 + j) * 32 + ch0);
            accv0[0][0] += fa0[j] * w.x; accv0[0][1] += fa0[j] * w.y;
            accv0[0][2] += fa0[j] * w.z; accv0[0][3] += fa0[j] * w.w;
            accv0[1][0] += fa1[j] * w.x; accv0[1][1] += fa1[j] * w.y;
            accv0[1][2] += fa1[j] * w.z; accv0[1][3] += fa1[j] * w.w;
            accv0[2][0] += fa2[j] * w.x; accv0[2][1] += fa2[j] * w.y;
            accv0[2][2] += fa2[j] * w.z; accv0[2][3] += fa2[j] * w.w;
            accv1[0][0] += fb0[j] * w.x; accv1[0][1] += fb0[j] * w.y;
            accv1[0][2] += fb0[j] * w.z; accv1[0][3] += fb0[j] * w.w;
            accv1[1][0] += fb1[j] * w.x; accv1[1][1] += fb1[j] * w.y;
            accv1[1][2] += fb1[j] * w.z; accv1[1][3] += fb1[j] * w.w;
            accv1[2][0] += fb2[j] * w.x; accv1[2][1] += fb2[j] * w.y;
            accv1[2][2] += fb2[j] * w.z; accv1[2][3] += fb2[j] * w.w;
        }
    }

    float at0[8], at1[8];
    {
        const float4 a0 = *reinterpret_cast<const float4*>(attrs + n0 * 8);
        const float4 a1 = *reinterpret_cast<const float4*>(attrs + n0 * 8 + 4);
        at0[0]=a0.x; at0[1]=a0.y; at0[2]=a0.z; at0[3]=a0.w;
        at0[4]=a1.x; at0[5]=a1.y; at0[6]=a1.z; at0[7]=a1.w;
        const float4 b0 = *reinterpret_cast<const float4*>(attrs + n1 * 8);
        const float4 b1 = *reinterpret_cast<const float4*>(attrs + n1 * 8 + 4);
        at1[0]=b0.x; at1[1]=b0.y; at1[2]=b0.z; at1[3]=b0.w;
        at1[4]=b1.x; at1[5]=b1.y; at1[6]=b1.z; at1[7]=b1.w;
    }
    const float* nvA = node_v + n0 * 96;
    const float* nvB = node_v + n1 * 96;
#pragma unroll 2
    for (int u = 0; u < 32; u++) {
        float mv0[4] = {0.f, 0.f, 0.f, 0.f};
        float mv1[4] = {0.f, 0.f, 0.f, 0.f};
#pragma unroll
        for (int a = 0; a < 8; a++) {
            const float4 w = *reinterpret_cast<const float4*>(sWscv + (u * 8 + a) * 32 + ch0);
            const float wa0 = at0[a];
            const float wa1 = at1[a];
            mv0[0] += wa0 * w.x; mv0[1] += wa0 * w.y;
            mv0[2] += wa0 * w.z; mv0[3] += wa0 * w.w;
            mv1[0] += wa1 * w.x; mv1[1] += wa1 * w.y;
            mv1[2] += wa1 * w.z; mv1[3] += wa1 * w.w;
        }
        const float va0 = nvA[u * 3 + 0], va1 = nvA[u * 3 + 1], va2 = nvA[u * 3 + 2];
        const float vb0 = nvB[u * 3 + 0], vb1 = nvB[u * 3 + 1], vb2 = nvB[u * 3 + 2];
#pragma unroll
        for (int j = 0; j < 4; j++) {
            accv0[0][j] += va0 * mv0[j];
            accv0[1][j] += va1 * mv0[j];
            accv0[2][j] += va2 * mv0[j];
            accv1[0][j] += vb0 * mv1[j];
            accv1[1][j] += vb1 * mv1[j];
            accv1[2][j] += vb2 * mv1[j];
        }
    }

    {
        float4* o4 = reinterpret_cast<float4*>(out + n0 * 128 + 32 + ch0 * 3);
#pragma unroll
        for (int g = 0; g < 3; g++) {
            const int f0 = g * 4;
            float4 o;
            o.x = accv0[(f0 + 0) % 3][(f0 + 0) / 3];
            o.y = accv0[(f0 + 1) % 3][(f0 + 1) / 3];
            o.z = accv0[(f0 + 2) % 3][(f0 + 2) / 3];
            o.w = accv0[(f0 + 3) % 3][(f0 + 3) / 3];
            o4[g] = o;
        }
    }
    {
        float4* o4 = reinterpret_cast<float4*>(out + n1 * 128 + 32 + ch0 * 3);
#pragma unroll
        for (int g = 0; g < 3; g++) {
            const int f0 = g * 4;
            float4 o;
            o.x = accv1[(f0 + 0) % 3][(f0 + 0) / 3];
            o.y = accv1[(f0 + 1) % 3][(f0 + 1) / 3];
            o.z = accv1[(f0 + 2) % 3][(f0 + 2) / 3];
            o.w = accv1[(f0 + 3) % 3][(f0 + 3) / 3];
            o4[g] = o;
        }
    }
}

// ---------------------------------------------------------------------------
extern "C" void kernel_launch(void* const* d_in, const int* in_sizes, int n_in,
                              void* d_out, int out_size) {
    const float* node_s     = (const float*)d_in[0];
    const float* node_v     = (const float*)d_in[1];
    const float* node_attrs = (const float*)d_in[2];
    const float* edge_emb   = (const float*)d_in[3];
    const float* edge_sh0   = (const float*)d_in[4];
    const float* edge_sh1   = (const float*)d_in[5];
    const float* W1_s       = (const float*)d_in[6];
    const float* W1_v       = (const float*)d_in[7];
    const float* Wm1        = (const float*)d_in[8];
    const float* Wm2        = (const float*)d_in[9];
    const float* W2_s       = (const float*)d_in[10];
    const float* W2_v       = (const float*)d_in[11];
    const float* Wsc_s      = (const float*)d_in[12];
    const float* Wsc_v      = (const float*)d_in[13];
    const int*   edge_src   = (const int*)d_in[14];
    const int*   edge_dst   = (const int*)d_in[15];
    float* out = (float*)d_out;

    // 1: count  2: scan(+re-zero cnt)  3: fill(+MLP L1)+lin1 merged
    count_kernel<<<(N_EDGES + 255) / 256, 256>>>(edge_dst);
    scan_kernel<<<1, 1024>>>();
    fill_lin1_kernel<<<FILL_BLOCKS + LIN1_BLOCKS, 256>>>(
        edge_dst, edge_src, edge_emb, edge_sh0, edge_sh1, Wm1,
        node_s, node_v, W1_s, W1_v);

    // 4 (profiled): warp-per-node gather + tensor product
    gather_tp<<<(N_NODES * 32 + 255) / 256, 256>>>(Wm2);

    // 5, 6: linear_2 + self-connection
    node_s_kernel<<<(N_NODES / 2 * 4 + 255) / 256, 256, 10240 * sizeof(float)>>>(
        node_s, node_attrs, W2_s, Wsc_s, out);
    node_v_kernel<<<(N_NODES / 2 * 8 + 255) / 256, 256, 11264 * sizeof(float)>>>(
        node_v, node_attrs, W2_v, Wsc_v, out);
}

// round 17
// speedup vs baseline: 1.1424x; 1.1424x over previous
#include <cuda_runtime.h>
#include <math.h>

#define N_NODES 50000
#define N_EDGES 800000
#define FILL_BLOCKS 3125          // ceil(800000/256)
#define LIN1_BLOCKS 6250          // 50000 nodes / 8 warps per block

#define INV_SQRT8  0.35355339059327373f
#define INV_SQRT32 0.17677669529663687f
#define CG_INV3    0.5773502691896258f   // 1/sqrt(3)
#define CG_INV2    0.7071067811865476f   // 1/sqrt(2)
#define MS_SCALE   0.125f                // 1/sqrt(64)
#define MV_SCALE   0.10206207261596575f  // 1/sqrt(96)
#define NSC_SCALE  0.0625f               // 1/sqrt(256)
#define NEIGH_INV  0.25f                 // 1/sqrt(16)

typedef unsigned long long u64;

// Scratch (static device memory — zero-initialized at module load)
__device__ __align__(16) float g_xs[N_NODES * 32];
__device__ __align__(16) float g_xv[N_NODES * 96];    // [N][3][32] comp-major
__device__ __align__(16) float g_aggs[N_NODES * 64];
__device__ __align__(16) float g_aggv[N_NODES * 288]; // [N][3][96] comp-major
__device__ int g_cnt[N_NODES];      // re-zeroed by scan_kernel each call
__device__ int g_off[N_NODES + 1];
__device__ int g_cur[N_NODES];
__device__ int g_psrc[N_EDGES];
__device__ __align__(16) float  g_ph[N_EDGES * 8];    // silu(emb@Wm1/sqrt8), CSR order
__device__ __align__(16) float4 g_psh[N_EDGES];

// ---- f32x2 packed helpers ----
__device__ __forceinline__ u64 pk2(float x) {
    u64 r;
    asm("mov.b64 %0, {%1, %1};" : "=l"(r) : "f"(x));
    return r;
}
__device__ __forceinline__ void fma2(u64& d, u64 a, u64 b) {
    asm("fma.rn.f32x2 %0, %1, %2, %0;" : "+l"(d) : "l"(a), "l"(b));
}
__device__ __forceinline__ u64 fma2r(u64 a, u64 b, u64 c) {
    u64 r;
    asm("fma.rn.f32x2 %0, %1, %2, %3;" : "=l"(r) : "l"(a), "l"(b), "l"(c));
    return r;
}
__device__ __forceinline__ u64 mul2(u64 a, u64 b) {
    u64 r;
    asm("mul.rn.f32x2 %0, %1, %2;" : "=l"(r) : "l"(a), "l"(b));
    return r;
}
__device__ __forceinline__ u64 add2(u64 a, u64 b) {
    u64 r;
    asm("add.rn.f32x2 %0, %1, %2;" : "=l"(r) : "l"(a), "l"(b));
    return r;
}

// ---------------------------------------------------------------------------
// Launch 1: count edges per destination
// ---------------------------------------------------------------------------
__global__ void count_kernel(const int* __restrict__ dst) {
    int e = blockIdx.x * blockDim.x + threadIdx.x;
    if (e < N_EDGES) atomicAdd(&g_cnt[dst[e]], 1);
}

// ---------------------------------------------------------------------------
// Launch 2: exclusive scan (hierarchical shuffle) + re-zero g_cnt
// ---------------------------------------------------------------------------
__global__ void scan_kernel() {
    __shared__ int wsum[32];
    const int CH = (N_NODES + 1023) / 1024;   // 49
    const int t = threadIdx.x;
    const int lo = t * CH;
    const int hi = min(lo + CH, N_NODES);
    int s = 0;
    for (int i = lo; i < hi; i++) s += g_cnt[i];

    const int lane = t & 31, wid = t >> 5;
    int v = s;
#pragma unroll
    for (int d = 1; d < 32; d <<= 1) {
        int o = __shfl_up_sync(0xffffffffu, v, d);
        if (lane >= d) v += o;
    }
    if (lane == 31) wsum[wid] = v;
    __syncthreads();
    if (wid == 0) {
        int w = wsum[lane];
#pragma unroll
        for (int d = 1; d < 32; d <<= 1) {
            int o = __shfl_up_sync(0xffffffffu, w, d);
            if (lane >= d) w += o;
        }
        wsum[lane] = w;
    }
    __syncthreads();
    int run = v - s + (wid ? wsum[wid - 1] : 0);
    for (int i = lo; i < hi; i++) {
        g_off[i] = run;
        g_cur[i] = run;
        run += g_cnt[i];
    }
    for (int i = lo; i < hi; i++) g_cnt[i] = 0;   // ready for next replay
    if (t == 0) g_off[N_NODES] = N_EDGES;
}

// ---------------------------------------------------------------------------
// Launch 3: MERGED fill (CSR permute + radial-MLP layer 1 + silu) + lin1.
// ---------------------------------------------------------------------------
__global__ void fill_lin1_kernel(const int* __restrict__ dst,
                                 const int* __restrict__ src,
                                 const float* __restrict__ emb,
                                 const float* __restrict__ sh0,
                                 const float* __restrict__ sh1,
                                 const float* __restrict__ Wm1,
                                 const float* __restrict__ node_s,
                                 const float* __restrict__ node_v,
                                 const float* __restrict__ W1s,
                                 const float* __restrict__ W1v) {
    __shared__ float sW[2048];
    __shared__ float sWm1[64];

    if (blockIdx.x < FILL_BLOCKS) {
        if (threadIdx.x < 64) sWm1[threadIdx.x] = Wm1[threadIdx.x];
        __syncthreads();

        int e = blockIdx.x * blockDim.x + threadIdx.x;
        if (e >= N_EDGES) return;
        int p = atomicAdd(&g_cur[dst[e]], 1);
        g_psrc[p] = src[e];

        const float4 e0 = *reinterpret_cast<const float4*>(emb + e * 8);
        const float4 e1 = *reinterpret_cast<const float4*>(emb + e * 8 + 4);
        const float em[8] = {e0.x, e0.y, e0.z, e0.w, e1.x, e1.y, e1.z, e1.w};

        float hh[8];
#pragma unroll
        for (int j = 0; j < 8; j++) {
            float a = 0.f;
#pragma unroll
            for (int k = 0; k < 8; k++)
                a += em[k] * sWm1[k * 8 + j];
            a *= INV_SQRT8;
            hh[j] = a / (1.f + expf(-a));   // silu (accurate exp)
        }
        float4* pw = reinterpret_cast<float4*>(g_ph + p * 8);
        pw[0] = make_float4(hh[0], hh[1], hh[2], hh[3]);
        pw[1] = make_float4(hh[4], hh[5], hh[6], hh[7]);

        g_psh[p] = make_float4(sh0[e], sh1[e * 3 + 0], sh1[e * 3 + 1], sh1[e * 3 + 2]);
    } else {
        float* sW1s = sW;
        float* sW1v = sW + 1024;
        for (int i = threadIdx.x; i < 1024; i += blockDim.x) {
            sW1s[i] = W1s[i];
            sW1v[i] = W1v[i];
        }
        __syncthreads();

        const int warp = (blockIdx.x - FILL_BLOCKS) * (blockDim.x >> 5) + (threadIdx.x >> 5);
        const int lane = threadIdx.x & 31;
        if (warp >= N_NODES) return;
        const int n = warp;

        float sl = node_s[n * 32 + lane];
        float acc = 0.f;
#pragma unroll
        for (int u = 0; u < 32; u++)
            acc += __shfl_sync(0xffffffffu, sl, u) * sW1s[u * 32 + lane];
        g_xs[n * 32 + lane] = acc * INV_SQRT32;

#pragma unroll
        for (int c = 0; c < 3; c++) {
            float vl = node_v[n * 96 + lane * 3 + c];
            float a = 0.f;
#pragma unroll
            for (int u = 0; u < 32; u++)
                a += __shfl_sync(0xffffffffu, vl, u) * sW1v[u * 32 + lane];
            g_xv[n * 96 + c * 32 + lane] = a * INV_SQRT32;
        }
    }
}

// ---------------------------------------------------------------------------
// Launch 4 (PROFILED SLOT): gather_tp — EDGE-BATCHED.
// WARP PER NODE: lane = es*16 + sub; 2 edge-slots x 16 channel-pair subs.
// Each slot processes 2 consecutive edges per iteration so every weight
// LDS.64 feeds TWO fma2 (edges A and B) -> weight crossbar traffic halves
// (20 wf/edge vs 40). Odd tail: phantom edge gets h=0 (all paths scale by
// w = sum h*W = 0), loads clamped in-bounds.
// __launch_bounds__(256, 2) -> 124-reg budget, no spills.
// CG_INV3 folded into Wm2 path 1, CG_INV2 into path 4 at staging time.
// ---------------------------------------------------------------------------
__global__ __launch_bounds__(256, 2) void gather_tp(const float* __restrict__ Wm2) {
    __shared__ __align__(16) float sWm2[1280];
    for (int i = threadIdx.x; i < 1280; i += blockDim.x) {
        const int p = (i % 160) >> 5;
        float sc = INV_SQRT8 * NEIGH_INV;
        if (p == 1) sc *= CG_INV3;
        if (p == 4) sc *= CG_INV2;
        sWm2[i] = Wm2[i] * sc;
    }
    __syncthreads();

    const int warp = (blockIdx.x * blockDim.x + threadIdx.x) >> 5;
    if (warp >= N_NODES) return;
    const int n = warp;
    const int lane = threadIdx.x & 31;
    const int es  = lane >> 4;       // edge slot 0..1
    const int sub = lane & 15;       // channel pair 0..15
    const int u0 = sub * 2;

    const int beg = g_off[n];
    const int end = g_off[n + 1];

    u64 A1 = 0, A2 = 0;
    u64 A3[3] = {0, 0, 0}, A4[3] = {0, 0, 0}, A5[3] = {0, 0, 0};

    for (int i0 = beg + es * 2; i0 < end; i0 += 4) {
        const bool v1 = (i0 + 1 < end);
        const int i1 = v1 ? (i0 + 1) : i0;

        // ---- payload (CSR-ordered, streaming) ----
        float4 hA0 = *reinterpret_cast<const float4*>(g_ph + i0 * 8);
        float4 hA1 = *reinterpret_cast<const float4*>(g_ph + i0 * 8 + 4);
        float4 hB0 = *reinterpret_cast<const float4*>(g_ph + i1 * 8);
        float4 hB1 = *reinterpret_cast<const float4*>(g_ph + i1 * 8 + 4);
        if (!v1) {
            hB0 = make_float4(0.f, 0.f, 0.f, 0.f);
            hB1 = make_float4(0.f, 0.f, 0.f, 0.f);
        }
        const float4 shA = g_psh[i0];
        const float4 shB = g_psh[i1];
        const int nsA = g_psrc[i0];
        const int nsB = g_psrc[i1];

        // ---- feature loads (issued early, independent) ----
        const u64 SA  = *reinterpret_cast<const u64*>(g_xs + nsA * 32 + u0);
        const u64 VXA = *reinterpret_cast<const u64*>(g_xv + nsA * 96 + u0);
        const u64 VYA = *reinterpret_cast<const u64*>(g_xv + nsA * 96 + 32 + u0);
        const u64 VZA = *reinterpret_cast<const u64*>(g_xv + nsA * 96 + 64 + u0);
        const u64 SB  = *reinterpret_cast<const u64*>(g_xs + nsB * 32 + u0);
        const u64 VXB = *reinterpret_cast<const u64*>(g_xv + nsB * 96 + u0);
        const u64 VYB = *reinterpret_cast<const u64*>(g_xv + nsB * 96 + 32 + u0);
        const u64 VZB = *reinterpret_cast<const u64*>(g_xv + nsB * 96 + 64 + u0);

        // ---- shared weight matvec: one LDS feeds both edges ----
        const float hva[8] = {hA0.x, hA0.y, hA0.z, hA0.w, hA1.x, hA1.y, hA1.z, hA1.w};
        const float hvb[8] = {hB0.x, hB0.y, hB0.z, hB0.w, hB1.x, hB1.y, hB1.z, hB1.w};
        u64 wA[5] = {0, 0, 0, 0, 0};
        u64 wB[5] = {0, 0, 0, 0, 0};
#pragma unroll
        for (int k = 0; k < 8; k++) {
            const u64 ha = pk2(hva[k]);
            const u64 hb = pk2(hvb[k]);
            const float* base = sWm2 + k * 160 + u0;
#pragma unroll
            for (int p = 0; p < 5; p++) {
                const u64 wv = *reinterpret_cast<const u64*>(base + p * 32);
                fma2(wA[p], ha, wv);
                fma2(wB[p], hb, wv);
            }
        }

        // ---- CG paths: edge A ----
        {
            const u64 q02 = pk2(shA.x);
            const u64 x2  = pk2(shA.y), y2 = pk2(shA.z), z2 = pk2(shA.w);
            const u64 nx2 = pk2(-shA.y), ny2 = pk2(-shA.z), nz2 = pk2(-shA.w);
            const u64 dot = fma2r(VXA, x2, fma2r(VYA, y2, mul2(VZA, z2)));
            const u64 cx = fma2r(VZA, ny2, mul2(VYA, z2));
            const u64 cy = fma2r(VXA, nz2, mul2(VZA, x2));
            const u64 cz = fma2r(VYA, nx2, mul2(VXA, y2));
            const u64 t1 = mul2(wA[0], SA);
            fma2(A1, t1, q02);
            fma2(A2, wA[1], dot);
            const u64 t3 = mul2(wA[2], SA);
            fma2(A3[0], t3, x2); fma2(A3[1], t3, y2); fma2(A3[2], t3, z2);
            const u64 t4 = mul2(wA[3], q02);
            fma2(A4[0], t4, VXA); fma2(A4[1], t4, VYA); fma2(A4[2], t4, VZA);
            fma2(A5[0], wA[4], cx); fma2(A5[1], wA[4], cy); fma2(A5[2], wA[4], cz);
        }
        // ---- CG paths: edge B (zero-h phantom on odd tail) ----
        {
            const u64 q02 = pk2(shB.x);
            const u64 x2  = pk2(shB.y), y2 = pk2(shB.z), z2 = pk2(shB.w);
            const u64 nx2 = pk2(-shB.y), ny2 = pk2(-shB.z), nz2 = pk2(-shB.w);
            const u64 dot = fma2r(VXB, x2, fma2r(VYB, y2, mul2(VZB, z2)));
            const u64 cx = fma2r(VZB, ny2, mul2(VYB, z2));
            const u64 cy = fma2r(VXB, nz2, mul2(VZB, x2));
            const u64 cz = fma2r(VYB, nx2, mul2(VXB, y2));
            const u64 t1 = mul2(wB[0], SB);
            fma2(A1, t1, q02);
            fma2(A2, wB[1], dot);
            const u64 t3 = mul2(wB[2], SB);
            fma2(A3[0], t3, x2); fma2(A3[1], t3, y2); fma2(A3[2], t3, z2);
            const u64 t4 = mul2(wB[3], q02);
            fma2(A4[0], t4, VXB); fma2(A4[1], t4, VYB); fma2(A4[2], t4, VZB);
            fma2(A5[0], wB[4], cx); fma2(A5[1], wB[4], cy); fma2(A5[2], wB[4], cz);
        }
    }

    // ---- butterfly reduce across the 2 edge slots (xor 16) ----
#define RED2(v) v = add2(v, __shfl_xor_sync(0xffffffffu, v, 16));
    RED2(A1) RED2(A2)
#pragma unroll
    for (int c = 0; c < 3; c++) {
        RED2(A3[c]) RED2(A4[c]) RED2(A5[c])
    }
#undef RED2

    if (es == 0) {
        *reinterpret_cast<u64*>(g_aggs + n * 64 + u0)      = A1;
        *reinterpret_cast<u64*>(g_aggs + n * 64 + 32 + u0) = A2;
#pragma unroll
        for (int c = 0; c < 3; c++) {
            float* av_base = g_aggv + n * 288 + c * 96 + u0;
            *reinterpret_cast<u64*>(av_base)      = A3[c];
            *reinterpret_cast<u64*>(av_base + 32) = A4[c];
            *reinterpret_cast<u64*>(av_base + 64) = A5[c];
        }
    }
}

// ---------------------------------------------------------------------------
// Launch 5: scalar output (2 nodes x 8 channels per thread)
// ---------------------------------------------------------------------------
__global__ __launch_bounds__(256) void node_s_kernel(
        const float* __restrict__ node_s,
        const float* __restrict__ attrs,
        const float* __restrict__ W2s,
        const float* __restrict__ Wscs,
        float* __restrict__ out) {
    extern __shared__ float sw[];
    float* sW2s  = sw;          // 2048 floats
    float* sWscs = sw + 2048;   // 8192 floats
    for (int i = threadIdx.x; i < 2048; i += blockDim.x)
        sW2s[i] = W2s[i] * MS_SCALE;
    for (int i = threadIdx.x; i < 8192; i += blockDim.x)
        sWscs[i] = Wscs[i] * NSC_SCALE;
    __syncthreads();

    const int gt = blockIdx.x * blockDim.x + threadIdx.x;
    const int pair = gt >> 2;
    if (pair >= N_NODES / 2) return;
    const int ch0 = (gt & 3) * 8;
    const int n0 = pair * 2;
    const int n1 = n0 + 1;

    float acc0[8], acc1[8];
#pragma unroll
    for (int j = 0; j < 8; j++) { acc0[j] = 0.f; acc1[j] = 0.f; }

    const float4* inA = reinterpret_cast<const float4*>(g_aggs + n0 * 64);
    const float4* inB = reinterpret_cast<const float4*>(g_aggs + n1 * 64);
#pragma unroll 4
    for (int k4 = 0; k4 < 16; k4++) {
        const float4 av = inA[k4];
        const float4 bv = inB[k4];
        const float a[4] = {av.x, av.y, av.z, av.w};
        const float b[4] = {bv.x, bv.y, bv.z, bv.w};
#pragma unroll
        for (int j = 0; j < 4; j++) {
            const float4* wr = reinterpret_cast<const float4*>(sW2s + (k4 * 4 + j) * 32 + ch0);
            const float4 w0 = wr[0];
            const float4 w1 = wr[1];
            acc0[0] += a[j] * w0.x; acc0[1] += a[j] * w0.y;
            acc0[2] += a[j] * w0.z; acc0[3] += a[j] * w0.w;
            acc0[4] += a[j] * w1.x; acc0[5] += a[j] * w1.y;
            acc0[6] += a[j] * w1.z; acc0[7] += a[j] * w1.w;
            acc1[0] += b[j] * w0.x; acc1[1] += b[j] * w0.y;
            acc1[2] += b[j] * w0.z; acc1[3] += b[j] * w0.w;
            acc1[4] += b[j] * w1.x; acc1[5] += b[j] * w1.y;
            acc1[6] += b[j] * w1.z; acc1[7] += b[j] * w1.w;
        }
    }

    float at0[8], at1[8];
    {
        const float4 a0 = *reinterpret_cast<const float4*>(attrs + n0 * 8);
        const float4 a1 = *reinterpret_cast<const float4*>(attrs + n0 * 8 + 4);
        at0[0]=a0.x; at0[1]=a0.y; at0[2]=a0.z; at0[3]=a0.w;
        at0[4]=a1.x; at0[5]=a1.y; at0[6]=a1.z; at0[7]=a1.w;
        const float4 b0 = *reinterpret_cast<const float4*>(attrs + n1 * 8);
        const float4 b1 = *reinterpret_cast<const float4*>(attrs + n1 * 8 + 4);
        at1[0]=b0.x; at1[1]=b0.y; at1[2]=b0.z; at1[3]=b0.w;
        at1[4]=b1.x; at1[5]=b1.y; at1[6]=b1.z; at1[7]=b1.w;
    }
    const float4* nsA = reinterpret_cast<const float4*>(node_s + n0 * 32);
    const float4* nsB = reinterpret_cast<const float4*>(node_s + n1 * 32);
#pragma unroll 2
    for (int u4 = 0; u4 < 8; u4++) {
        const float4 sa = nsA[u4];
        const float4 sb = nsB[u4];
        const float sua[4] = {sa.x, sa.y, sa.z, sa.w};
        const float sub_[4] = {sb.x, sb.y, sb.z, sb.w};
#pragma unroll
        for (int j = 0; j < 4; j++) {
            const int u = u4 * 4 + j;
#pragma unroll
            for (int a = 0; a < 8; a++) {
                const float za = sua[j] * at0[a];
                const float zb = sub_[j] * at1[a];
                const float4* wr = reinterpret_cast<const float4*>(sWscs + (u * 8 + a) * 32 + ch0);
                const float4 w0 = wr[0];
                const float4 w1 = wr[1];
                acc0[0] += za * w0.x; acc0[1] += za * w0.y;
                acc0[2] += za * w0.z; acc0[3] += za * w0.w;
                acc0[4] += za * w1.x; acc0[5] += za * w1.y;
                acc0[6] += za * w1.z; acc0[7] += za * w1.w;
                acc1[0] += zb * w0.x; acc1[1] += zb * w0.y;
                acc1[2] += zb * w0.z; acc1[3] += zb * w0.w;
                acc1[4] += zb * w1.x; acc1[5] += zb * w1.y;
                acc1[6] += zb * w1.z; acc1[7] += zb * w1.w;
            }
        }
    }

    float4* o0 = reinterpret_cast<float4*>(out + n0 * 128 + ch0);
    o0[0] = make_float4(acc0[0], acc0[1], acc0[2], acc0[3]);
    o0[1] = make_float4(acc0[4], acc0[5], acc0[6], acc0[7]);
    float4* o1 = reinterpret_cast<float4*>(out + n1 * 128 + ch0);
    o1[0] = make_float4(acc1[0], acc1[1], acc1[2], acc1[3]);
    o1[1] = make_float4(acc1[4], acc1[5], acc1[6], acc1[7]);
}

// ---------------------------------------------------------------------------
// Launch 6: vector output (2 nodes x 4 channels per thread)
// ---------------------------------------------------------------------------
__global__ __launch_bounds__(256) void node_v_kernel(
        const float* __restrict__ node_v,
        const float* __restrict__ attrs,
        const float* __restrict__ W2v,
        const float* __restrict__ Wscv,
        float* __restrict__ out) {
    extern __shared__ float sw[];
    float* sW2v  = sw;          // 3072 floats
    float* sWscv = sw + 3072;   // 8192 floats
    for (int i = threadIdx.x; i < 3072; i += blockDim.x)
        sW2v[i] = W2v[i] * MV_SCALE;
    for (int i = threadIdx.x; i < 8192; i += blockDim.x)
        sWscv[i] = Wscv[i] * NSC_SCALE;
    __syncthreads();

    const int gt = blockIdx.x * blockDim.x + threadIdx.x;
    const int pair = gt >> 3;
    if (pair >= N_NODES / 2) return;
    const int ch0 = (gt & 7) * 4;
    const int n0 = pair * 2;
    const int n1 = n0 + 1;

    float accv0[3][4], accv1[3][4];
#pragma unroll
    for (int c = 0; c < 3; c++)
#pragma unroll
        for (int j = 0; j < 4; j++) { accv0[c][j] = 0.f; accv1[c][j] = 0.f; }

    const float4* iA0 = reinterpret_cast<const float4*>(g_aggv + n0 * 288);
    const float4* iA1 = reinterpret_cast<const float4*>(g_aggv + n0 * 288 + 96);
    const float4* iA2 = reinterpret_cast<const float4*>(g_aggv + n0 * 288 + 192);
    const float4* iB0 = reinterpret_cast<const float4*>(g_aggv + n1 * 288);
    const float4* iB1 = reinterpret_cast<const float4*>(g_aggv + n1 * 288 + 96);
    const float4* iB2 = reinterpret_cast<const float4*>(g_aggv + n1 * 288 + 192);
#pragma unroll 2
    for (int k4 = 0; k4 < 24; k4++) {
        const float4 a0 = iA0[k4], a1 = iA1[k4], a2 = iA2[k4];
        const float4 b0 = iB0[k4], b1 = iB1[k4], b2 = iB2[k4];
        const float fa0[4] = {a0.x, a0.y, a0.z, a0.w};
        const float fa1[4] = {a1.x, a1.y, a1.z, a1.w};
        const float fa2[4] = {a2.x, a2.y, a2.z, a2.w};
        const float fb0[4] = {b0.x, b0.y, b0.z, b0.w};
        const float fb1[4] = {b1.x, b1.y, b1.z, b1.w};
        const float fb2[4] = {b2.x, b2.y, b2.z, b2.w};
#pragma unroll
        for (int j = 0; j < 4; j++) {
            const float4 w = *reinterpret_cast<const float4*>(sW2v + (k4 * 4 + j) * 32 + ch0);
            accv0[0][0] += fa0[j] * w.x; accv0[0][1] += fa0[j] * w.y;
            accv0[0][2] += fa0[j] * w.z; accv0[0][3] += fa0[j] * w.w;
            accv0[1][0] += fa1[j] * w.x; accv0[1][1] += fa1[j] * w.y;
            accv0[1][2] += fa1[j] * w.z; accv0[1][3] += fa1[j] * w.w;
            accv0[2][0] += fa2[j] * w.x; accv0[2][1] += fa2[j] * w.y;
            accv0[2][2] += fa2[j] * w.z; accv0[2][3] += fa2[j] * w.w;
            accv1[0][0] += fb0[j] * w.x; accv1[0][1] += fb0[j] * w.y;
            accv1[0][2] += fb0[j] * w.z; accv1[0][3] += fb0[j] * w.w;
            accv1[1][0] += fb1[j] * w.x; accv1[1][1] += fb1[j] * w.y;
            accv1[1][2] += fb1[j] * w.z; accv1[1][3] += fb1[j] * w.w;
            accv1[2][0] += fb2[j] * w.x; accv1[2][1] += fb2[j] * w.y;
            accv1[2][2] += fb2[j] * w.z; accv1[2][3] += fb2[j] * w.w;
        }
    }

    float at0[8], at1[8];
    {
        const float4 a0 = *reinterpret_cast<const float4*>(attrs + n0 * 8);
        const float4 a1 = *reinterpret_cast<const float4*>(attrs + n0 * 8 + 4);
        at0[0]=a0.x; at0[1]=a0.y; at0[2]=a0.z; at0[3]=a0.w;
        at0[4]=a1.x; at0[5]=a1.y; at0[6]=a1.z; at0[7]=a1.w;
        const float4 b0 = *reinterpret_cast<const float4*>(attrs + n1 * 8);
        const float4 b1 = *reinterpret_cast<const float4*>(attrs + n1 * 8 + 4);
        at1[0]=b0.x; at1[1]=b0.y; at1[2]=b0.z; at1[3]=b0.w;
        at1[4]=b1.x; at1[5]=b1.y; at1[6]=b1.z; at1[7]=b1.w;
    }
    const float* nvA = node_v + n0 * 96;
    const float* nvB = node_v + n1 * 96;
#pragma unroll 2
    for (int u = 0; u < 32; u++) {
        float mv0[4] = {0.f, 0.f, 0.f, 0.f};
        float mv1[4] = {0.f, 0.f, 0.f, 0.f};
#pragma unroll
        for (int a = 0; a < 8; a++) {
            const float4 w = *reinterpret_cast<const float4*>(sWscv + (u * 8 + a) * 32 + ch0);
            const float wa0 = at0[a];
            const float wa1 = at1[a];
            mv0[0] += wa0 * w.x; mv0[1] += wa0 * w.y;
            mv0[2] += wa0 * w.z; mv0[3] += wa0 * w.w;
            mv1[0] += wa1 * w.x; mv1[1] += wa1 * w.y;
            mv1[2] += wa1 * w.z; mv1[3] += wa1 * w.w;
        }
        const float va0 = nvA[u * 3 + 0], va1 = nvA[u * 3 + 1], va2 = nvA[u * 3 + 2];
        const float vb0 = nvB[u * 3 + 0], vb1 = nvB[u * 3 + 1], vb2 = nvB[u * 3 + 2];
#pragma unroll
        for (int j = 0; j < 4; j++) {
            accv0[0][j] += va0 * mv0[j];
            accv0[1][j] += va1 * mv0[j];
            accv0[2][j] += va2 * mv0[j];
            accv1[0][j] += vb0 * mv1[j];
            accv1[1][j] += vb1 * mv1[j];
            accv1[2][j] += vb2 * mv1[j];
        }
    }

    {
        float4* o4 = reinterpret_cast<float4*>(out + n0 * 128 + 32 + ch0 * 3);
#pragma unroll
        for (int g = 0; g < 3; g++) {
            const int f0 = g * 4;
            float4 o;
            o.x = accv0[(f0 + 0) % 3][(f0 + 0) / 3];
            o.y = accv0[(f0 + 1) % 3][(f0 + 1) / 3];
            o.z = accv0[(f0 + 2) % 3][(f0 + 2) / 3];
            o.w = accv0[(f0 + 3) % 3][(f0 + 3) / 3];
            o4[g] = o;
        }
    }
    {
        float4* o4 = reinterpret_cast<float4*>(out + n1 * 128 + 32 + ch0 * 3);
#pragma unroll
        for (int g = 0; g < 3; g++) {
            const int f0 = g * 4;
            float4 o;
            o.x = accv1[(f0 + 0) % 3][(f0 + 0) / 3];
            o.y = accv1[(f0 + 1) % 3][(f0 + 1) / 3];
            o.z = accv1[(f0 + 2) % 3][(f0 + 2) / 3];
            o.w = accv1[(f0 + 3) % 3][(f0 + 3) / 3];
            o4[g] = o;
        }
    }
}

// ---------------------------------------------------------------------------
extern "C" void kernel_launch(void* const* d_in, const int* in_sizes, int n_in,
                              void* d_out, int out_size) {
    const float* node_s     = (const float*)d_in[0];
    const float* node_v     = (const float*)d_in[1];
    const float* node_attrs = (const float*)d_in[2];
    const float* edge_emb   = (const float*)d_in[3];
    const float* edge_sh0   = (const float*)d_in[4];
    const float* edge_sh1   = (const float*)d_in[5];
    const float* W1_s       = (const float*)d_in[6];
    const float* W1_v       = (const float*)d_in[7];
    const float* Wm1        = (const float*)d_in[8];
    const float* Wm2        = (const float*)d_in[9];
    const float* W2_s       = (const float*)d_in[10];
    const float* W2_v       = (const float*)d_in[11];
    const float* Wsc_s      = (const float*)d_in[12];
    const float* Wsc_v      = (const float*)d_in[13];
    const int*   edge_src   = (const int*)d_in[14];
    const int*   edge_dst   = (const int*)d_in[15];
    float* out = (float*)d_out;

    // 1: count  2: scan(+re-zero cnt)  3: fill(+MLP L1)+lin1 merged
    count_kernel<<<(N_EDGES + 255) / 256, 256>>>(edge_dst);
    scan_kernel<<<1, 1024>>>();
    fill_lin1_kernel<<<FILL_BLOCKS + LIN1_BLOCKS, 256>>>(
        edge_dst, edge_src, edge_emb, edge_sh0, edge_sh1, Wm1,
        node_s, node_v, W1_s, W1_v);

    // 4 (profiled): edge-batched warp-per-node gather + tensor product
    gather_tp<<<(N_NODES * 32 + 255) / 256, 256>>>(Wm2);

    // 5, 6: linear_2 + self-connection
    node_s_kernel<<<(N_NODES / 2 * 4 + 255) / 256, 256, 10240 * sizeof(float)>>>(
        node_s, node_attrs, W2_s, Wsc_s, out);
    node_v_kernel<<<(N_NODES / 2 * 8 + 255) / 256, 256, 11264 * sizeof(float)>>>(
        node_v, node_attrs, W2_v, Wsc_v, out);
}